// round 16
// baseline (speedup 1.0000x reference)
#include <cuda_runtime.h>
#include <cuda_fp16.h>
#include <math.h>

// ---------------------------------------------------------------------------
// Problem constants
// ---------------------------------------------------------------------------
#define BATCH   2
#define SEQ     2048
#define HIDDEN  1024
#define Q_OUT   2048
#define KV_OUT  1024
#define HDIM    128
#define NQ      16
#define NKV     8
#define TOKENS  (BATCH*SEQ)          // 4096

// ---------------------------------------------------------------------------
// Scratch. All half2-packed uints, mma-fragment-ordered, PAIRED for LDS.128:
//   A-frag:  [mtile][ktile][lane(32)][reg(4)]
//   B-pair:  [kt][np=ng/2][lane(32)][reg(4)] reg=(ng&1)*2+r
//   K-pair:  [ktile][ksf(8)][jp(4)][lane][4]  reg=(jf&1)*2+r
//   V-pair:  [ktile][ksv(4)][jp(8)][lane][4]  reg=(jf&1)*2+r
//   Q-frag:  [qblock(tok/16)][h][ks(8)][lane][reg(4)]
// ---------------------------------------------------------------------------
__device__ __align__(256) unsigned g_xh [TOKENS/16 * 64 * 128];
__device__ __align__(256) unsigned g_wqh[64 * 128 * 128];            // npN=128
__device__ __align__(256) unsigned g_wkh[64 * 64 * 128];             // npN=64
__device__ __align__(256) unsigned g_wvh[64 * 64 * 128];
__device__ __align__(256) unsigned g_woh[128 * 64 * 128];
__device__ __align__(256) unsigned g_qh [TOKENS/16 * 16 * 8 * 128];  // Q frag
__device__ __align__(256) unsigned g_kTh[(size_t)BATCH * NKV * 32 * 4096];
__device__ __align__(256) unsigned g_vTh[(size_t)BATCH * NKV * 32 * 4096];
__device__ __align__(256) unsigned g_oh [TOKENS/16 * 128 * 128];     // wo A-frag
__device__ float g_cosT[SEQ * 64];
__device__ float g_sinT[SEQ * 64];

// ---------------------------------------------------------------------------
// helpers
// ---------------------------------------------------------------------------
__device__ __forceinline__ unsigned pack_h2(float lo, float hi) {
    unsigned u;
    asm("cvt.rn.f16x2.f32 %0, %2, %1;" : "=r"(u) : "f"(lo), "f"(hi));
    return u;
}

__device__ __forceinline__ float ex2f(float x) {
    float r;
    asm("ex2.approx.f32 %0, %1;" : "=f"(r) : "f"(x));
    return r;
}

__device__ __forceinline__ void mma_f16(float* c, const unsigned* a,
                                        unsigned b0, unsigned b1) {
    asm("mma.sync.aligned.m16n8k16.row.col.f32.f16.f16.f32 "
        "{%0,%1,%2,%3}, {%4,%5,%6,%7}, {%8,%9}, {%0,%1,%2,%3};"
        : "+f"(c[0]), "+f"(c[1]), "+f"(c[2]), "+f"(c[3])
        : "r"(a[0]), "r"(a[1]), "r"(a[2]), "r"(a[3]), "r"(b0), "r"(b1));
}

__device__ __forceinline__ void cp_async16(unsigned dst_smem, const void* src) {
    asm volatile("cp.async.cg.shared.global [%0], [%1], 16;\n"
                 :: "r"(dst_smem), "l"(src));
}
#define CP_COMMIT()  asm volatile("cp.async.commit_group;\n" ::: "memory")
#define CP_WAIT(N)   asm volatile("cp.async.wait_group %0;\n" :: "n"(N) : "memory")

// ---------------------------------------------------------------------------
// Fused prep (coalesced): x -> A-frag | weights -> B-pair | rope table
// ---------------------------------------------------------------------------
__global__ __launch_bounds__(256) void prep_kernel(
    const float* __restrict__ x,
    const float* __restrict__ Wq, const float* __restrict__ Wk,
    const float* __restrict__ Wv, const float* __restrict__ Wo)
{
    __shared__ float sm[16 * 132];
    int bid = blockIdx.x;
    int tid = threadIdx.x;

    if (bid < 2048) {
        int mtile = bid >> 3, ktg = bid & 7;
        const float* src = x + (size_t)mtile * 16 * 1024 + ktg * 128;
#pragma unroll
        for (int it = 0; it < 2; it++) {
            int p = tid + it * 256;
            int row = p >> 5, c4 = (p & 31) * 4;
            float4 v = *(const float4*)(src + (size_t)row * 1024 + c4);
            *(float4*)(sm + row * 132 + c4) = v;
        }
        __syncthreads();
#pragma unroll
        for (int it = 0; it < 4; it++) {
            int j = tid + it * 256;
            int ktl = j >> 7, i = j & 127;
            int gg = i >> 4, tt = (i >> 2) & 3, reg = i & 3;
            int ml = gg + (reg & 1) * 8;
            int cl = 2 * (ktl * 8 + tt + ((reg >> 1) & 1) * 4);
            g_xh[((size_t)mtile * 64 + ktg * 8 + ktl) * 128 + i] =
                pack_h2(sm[ml * 132 + cl], sm[ml * 132 + cl + 1]);
        }
        return;
    }
    if (bid < 8192) {
        int wb = bid - 2048;
        const float* src; unsigned* dst; int N, npN, kt, ngg;
        if (wb < 2048)      { src = Wq; dst = g_wqh; N = 2048; npN = 128; kt = wb >> 5; ngg = wb & 31; }
        else if (wb < 3072) { wb -= 2048; src = Wk; dst = g_wkh; N = 1024; npN = 64; kt = wb >> 4; ngg = wb & 15; }
        else if (wb < 4096) { wb -= 3072; src = Wv; dst = g_wvh; N = 1024; npN = 64; kt = wb >> 4; ngg = wb & 15; }
        else                { wb -= 4096; src = Wo; dst = g_woh; N = 1024; npN = 64; kt = wb >> 4; ngg = wb & 15; }
        {
            int row = tid >> 4, c4 = (tid & 15) * 4;
            float4 v = *(const float4*)(src + (size_t)(kt * 16 + row) * N + ngg * 64 + c4);
            *(float4*)(sm + row * 68 + c4) = v;
        }
        __syncthreads();
#pragma unroll
        for (int it = 0; it < 2; it++) {
            int j = tid + it * 256;                 // [0,512)
            int ngl = j >> 6, i = j & 63;
            int gg = i >> 3, tt = (i >> 1) & 3, reg = i & 1;
            int rl = 2 * (tt + reg * 4);
            int cl = ngl * 8 + gg;
            int ng = ngg * 8 + ngl;
            int lane = gg * 4 + tt;
            dst[((size_t)kt * npN + (ng >> 1)) * 128 + lane * 4 + (ng & 1) * 2 + reg] =
                pack_h2(sm[rl * 68 + cl], sm[(rl + 1) * 68 + cl]);
        }
        return;
    }
    int id = (bid - 8192) * 256 + tid;
    int t = id >> 6, j = id & 63;
    float e = (float)j * (1.0f / 64.0f);
    float inv = exp2f(-e * 13.287712379549449f);
    float a = (float)t * inv;
    float s, c;
    sincosf(a, &s, &c);
    g_cosT[t * 64 + j] = c;
    g_sinT[t * 64 + j] = s;
}

// ---------------------------------------------------------------------------
// fp16 GEMM core v7: 128 threads, 64x64 warp tiles, all LDS.128.
// NKT = A ktile stride (per mtile); nkt = ktiles to process this call.
// ---------------------------------------------------------------------------
#define AB_BUF 2048
#define GEMM_SMEM ((6 * AB_BUF + 512) * 4)

__device__ __forceinline__ void gemm_core_h(
    const unsigned* __restrict__ Ah, const unsigned* __restrict__ Bh,
    int NKT, int nkt, int npN, int mtile0, int np0,
    unsigned* As, unsigned* Bs, float acc[4][8][4])
{
    int tid = threadIdx.x;
    int lane = tid & 31;
    int wi = tid >> 5;
    int warp_mi = (wi & 1) * 4;
    int wq = wi >> 1;

    unsigned as_u = (unsigned)__cvta_generic_to_shared(As);
    unsigned bs_u = (unsigned)__cvta_generic_to_shared(Bs);

    const int nsteps = nkt >> 1;

#define GEMM_ISSUE(s, buf) do {                                               \
        unsigned a_base = as_u + (buf) * (AB_BUF * 4);                        \
        unsigned b_base = bs_u + (buf) * (AB_BUF * 4);                        \
        _Pragma("unroll")                                                     \
        for (int it = 0; it < 4; it++) {                                      \
            int c = tid + it * 128;                                           \
            cp_async16(a_base + c * 16,                                       \
                Ah + ((size_t)(mtile0 + (c >> 6)) * NKT                       \
                      + 2 * (s) + ((c >> 5) & 1)) * 128 + (c & 31) * 4);      \
            cp_async16(b_base + c * 16,                                       \
                Bh + ((size_t)(2 * (s) + (c >> 8)) * npN + np0) * 128         \
                      + (c & 255) * 4);                                       \
        }                                                                     \
        CP_COMMIT();                                                          \
    } while (0)

    GEMM_ISSUE(0, 0);
    GEMM_ISSUE(1, 1);

    int buf = 0;
    for (int s = 0; s < nsteps; s++) {
        CP_WAIT(1);
        __syncthreads();

        if (s + 2 < nsteps) {
            int nb = buf + 2; if (nb >= 3) nb -= 3;
            GEMM_ISSUE(s + 2, nb);
        } else {
            CP_COMMIT();
        }

        unsigned* Ab = As + buf * AB_BUF;
        unsigned* Bb = Bs + buf * AB_BUF;
#pragma unroll
        for (int ks = 0; ks < 2; ks++) {
            unsigned af[4][4];
            uint4 bf4[4];
#pragma unroll
            for (int mi = 0; mi < 4; mi++) {
                uint4 a4 = *(uint4*)(Ab + ((warp_mi + mi) * 2 + ks) * 128 + lane * 4);
                af[mi][0] = a4.x; af[mi][1] = a4.y; af[mi][2] = a4.z; af[mi][3] = a4.w;
            }
#pragma unroll
            for (int pq = 0; pq < 4; pq++) {
                int npl = wq * 2 + (pq & 1) + (pq >> 1) * 4;
                bf4[pq] = *(uint4*)(Bb + ((ks * 8 + npl) * 32 + lane) * 4);
            }
#pragma unroll
            for (int mi = 0; mi < 4; mi++)
#pragma unroll
                for (int nj = 0; nj < 8; nj++) {
                    int pq = ((nj & 3) >> 1) + (nj >> 2) * 2;
                    unsigned b0 = (nj & 1) ? bf4[pq].z : bf4[pq].x;
                    unsigned b1 = (nj & 1) ? bf4[pq].w : bf4[pq].y;
                    mma_f16(acc[mi][nj], af[mi], b0, b1);
                }
        }

        buf++; if (buf == 3) buf = 0;
    }
#undef GEMM_ISSUE
}

// ---------------------------------------------------------------------------
// Fused QKV GEMM + RMSNorm + RoPE -> paired flash fragment layouts (R14)
// ---------------------------------------------------------------------------
__global__ __launch_bounds__(128, 2) void qkv_h_kernel(
    const float* __restrict__ qw, const float* __restrict__ kw)
{
    extern __shared__ unsigned dsm[];
    unsigned* As = dsm;
    unsigned* Bs = As + 3 * AB_BUF;
    float (*sred)[2] = (float(*)[2])(Bs + 3 * AB_BUF);

    int bx = blockIdx.x;
    const unsigned* Bh; const float* w; int npN, np0, mode, head;
    if (bx < 16)      { Bh = g_wqh; npN = 128; np0 = bx * 8;        mode = 0; head = bx;      w = qw; }
    else if (bx < 24) { Bh = g_wkh; npN = 64;  np0 = (bx - 16) * 8; mode = 1; head = bx - 16; w = kw; }
    else              { Bh = g_wvh; npN = 64;  np0 = (bx - 24) * 8; mode = 2; head = bx - 24; w = qw; }

    int row0 = blockIdx.y * 128;

    float acc[4][8][4];
#pragma unroll
    for (int mi = 0; mi < 4; mi++)
#pragma unroll
        for (int nj = 0; nj < 8; nj++)
#pragma unroll
            for (int c = 0; c < 4; c++) acc[mi][nj][c] = 0.0f;

    gemm_core_h(g_xh, Bh, 64, 64, npN, row0 >> 4, np0, As, Bs, acc);

    int tid = threadIdx.x;
    int lane = tid & 31;
    int wi = tid >> 5;
    int g = lane >> 2;
    int t = lane & 3;
    int warp_m = (wi & 1) * 64;
    int wq = wi >> 1;

    if (mode != 2) {
        float ssl[4][2];
#pragma unroll
        for (int mi = 0; mi < 4; mi++)
#pragma unroll
            for (int hf = 0; hf < 2; hf++) {
                float s = 0.0f;
#pragma unroll
                for (int nj = 0; nj < 8; nj++)
#pragma unroll
                    for (int b2 = 0; b2 < 2; b2++) {
                        float v = acc[mi][nj][hf * 2 + b2];
                        s = fmaf(v, v, s);
                    }
                s += __shfl_xor_sync(0xffffffffu, s, 1);
                s += __shfl_xor_sync(0xffffffffu, s, 2);
                ssl[mi][hf] = s;
            }
        __syncthreads();
        if (t == 0) {
#pragma unroll
            for (int mi = 0; mi < 4; mi++)
#pragma unroll
                for (int hf = 0; hf < 2; hf++)
                    sred[warp_m + mi * 16 + g + 8 * hf][wq] = ssl[mi][hf];
        }
        __syncthreads();

        float wv[8][2];
#pragma unroll
        for (int nj = 0; nj < 8; nj++) {
            int noff = (nj & 3) * 8 + (nj >> 2) * 64;
            wv[nj][0] = w[wq * 32 + noff + 2 * t];
            wv[nj][1] = w[wq * 32 + noff + 2 * t + 1];
        }

        const float qscale = 0.12751753972083234f;  // 1/sqrt(128)*log2e

#pragma unroll
        for (int mi = 0; mi < 4; mi++)
#pragma unroll
            for (int hf = 0; hf < 2; hf++) {
                int row = warp_m + mi * 16 + g + 8 * hf;
                float tot = sred[row][0] + sred[row][1];
                float r = rsqrtf(tot * (1.0f / 128.0f) + 1e-6f);
                int token = row0 + row;
                int tp = token & (SEQ - 1);
                int bb = token >> 11;

                float nv[8][2];
#pragma unroll
                for (int nj = 0; nj < 8; nj++)
#pragma unroll
                    for (int b2 = 0; b2 < 2; b2++)
                        nv[nj][b2] = acc[mi][nj][hf * 2 + b2] * r * wv[nj][b2];

#pragma unroll
                for (int nj = 0; nj < 8; nj++) {
                    int a = nj & 3, bq = nj >> 2;
                    int ci = wq * 32 + a * 8 + 2 * t;       // d & 63
                    float c0 = g_cosT[tp * 64 + ci];
                    float s0 = g_sinT[tp * 64 + ci];
                    float c1 = g_cosT[tp * 64 + ci + 1];
                    float s1 = g_sinT[tp * 64 + ci + 1];
                    float rot0 = (nj < 4) ? -nv[nj + 4][0] : nv[nj - 4][0];
                    float rot1 = (nj < 4) ? -nv[nj + 4][1] : nv[nj - 4][1];
                    float o0 = nv[nj][0] * c0 + rot0 * s0;
                    float o1 = nv[nj][1] * c1 + rot1 * s1;
                    if (mode == 0) {
                        int ks = wq * 2 + (a >> 1) + 4 * bq;
                        int qblock = token >> 4;
                        int reg = hf + (a & 1) * 2;
                        g_qh[((((size_t)qblock * 16 + head) * 8 + ks) * 32 + lane) * 4 + reg] =
                            pack_h2(o0 * qscale, o1 * qscale);
                    } else {
                        int dd = wq * 16 + a * 4 + bq * 32 + t;
                        int ksf = dd >> 3, rr = dd & 7;
                        int tf = rr & 3, regf = rr >> 2;
                        int ktile = tp >> 6;
                        int jf = (tp >> 3) & 7, gf = tp & 7;
                        size_t idx = ((size_t)(bb * NKV + head) * 32 + ktile) * 4096
                                   + ((ksf * 4 + (jf >> 1)) * 32 + gf * 4 + tf) * 4
                                   + (jf & 1) * 2 + regf;
                        g_kTh[idx] = pack_h2(o0, o1);
                    }
                }
            }
    } else {
#pragma unroll
        for (int mi = 0; mi < 4; mi++)
#pragma unroll
            for (int hf = 0; hf < 2; hf++) {
                int row = warp_m + mi * 16 + g + 8 * hf;
                int token = row0 + row;
                int tp = token & (SEQ - 1);
                int bb = token >> 11;
                int ktile = tp >> 6;
                int kkl = (tp & 63) >> 1;
                int ksv = kkl >> 3, rr = kkl & 7;
                int tf = rr & 3, regf = rr >> 2;
#pragma unroll
                for (int nj = 0; nj < 8; nj++) {
                    int noff = (nj & 3) * 8 + (nj >> 2) * 64;
                    float v0 = acc[mi][nj][hf * 2 + 0];
                    float v1 = acc[mi][nj][hf * 2 + 1];
                    float n0 = __shfl_down_sync(0xffffffffu, v0, 4);
                    float n1 = __shfl_down_sync(0xffffffffu, v1, 4);
                    if (!(g & 1)) {
                        int d0 = wq * 32 + noff + 2 * t;
                        int jf = d0 >> 3, gf = d0 & 7;
                        size_t idx = ((size_t)(bb * NKV + head) * 32 + ktile) * 4096
                                   + ((ksv * 8 + (jf >> 1)) * 32 + gf * 4 + tf) * 4
                                   + (jf & 1) * 2 + regf;
                        g_vTh[idx]      = pack_h2(v0, n0);
                        g_vTh[idx + 16] = pack_h2(v1, n1);
                    }
                }
            }
    }
}

// ---------------------------------------------------------------------------
// Wo GEMM, SPLIT-K=2: grid (8, 32, 2). Each CTA does 64 of 128 ktiles and
// atomicAdds its partial into the pre-zeroed output.
// ---------------------------------------------------------------------------
__global__ __launch_bounds__(128, 2) void wo_h_kernel(float* __restrict__ C)
{
    extern __shared__ unsigned dsm[];
    unsigned* As = dsm;
    unsigned* Bs = As + 3 * AB_BUF;

    int row0 = blockIdx.y * 128;
    int col0 = blockIdx.x * 128;
    int ksp  = blockIdx.z;          // 0 or 1

    float acc[4][8][4];
#pragma unroll
    for (int mi = 0; mi < 4; mi++)
#pragma unroll
        for (int nj = 0; nj < 8; nj++)
#pragma unroll
            for (int c = 0; c < 4; c++) acc[mi][nj][c] = 0.0f;

    gemm_core_h(g_oh + (size_t)ksp * 64 * 128, g_woh + (size_t)ksp * 64 * 64 * 128,
                128, 64, 64, row0 >> 4, col0 >> 4, As, Bs, acc);

    int tid = threadIdx.x;
    int lane = tid & 31;
    int wi = tid >> 5;
    int g = lane >> 2;
    int t = lane & 3;
    int warp_m = (wi & 1) * 64;
    int wq = wi >> 1;

#pragma unroll
    for (int mi = 0; mi < 4; mi++)
#pragma unroll
        for (int hf = 0; hf < 2; hf++) {
            int row = row0 + warp_m + mi * 16 + g + 8 * hf;
#pragma unroll
            for (int nj = 0; nj < 8; nj++) {
                int noff = (nj & 3) * 8 + (nj >> 2) * 64;
                float* dst = C + (size_t)row * HIDDEN + col0 + wq * 32 + noff + 2 * t;
                atomicAdd(dst,     acc[mi][nj][hf * 2 + 0]);
                atomicAdd(dst + 1, acc[mi][nj][hf * 2 + 1]);
            }
        }
}

// ---------------------------------------------------------------------------
// Flash attention (R14, proven): paired K/V layouts, Q-frag LDG.128,
// fixed-max base-2 softmax, 64 q-rows / 128 threads, occupancy 3.
// ---------------------------------------------------------------------------
#define FA_BUF 8192
#define FA_SMEM (2 * FA_BUF * 4)

__global__ __launch_bounds__(128, 3) void flash_h_kernel()
{
    extern __shared__ unsigned smu[];
    unsigned smu_u = (unsigned)__cvta_generic_to_shared(smu);

    int qt = gridDim.x - 1 - blockIdx.x;   // big tiles first
    int h  = blockIdx.y;
    int b  = blockIdx.z;
    int kvh = h >> 1;
    int q0 = qt * 64;

    int tid = threadIdx.x;
    int w = tid >> 5;
    int lane = tid & 31;
    int g = lane >> 2;
    int t = lane & 3;

    int row0 = w * 16 + g;
    int row1 = row0 + 8;
    int qrow0 = q0 + row0;
    int qrow1 = q0 + row1;

    const unsigned* Kf = g_kTh + (size_t)(b * NKV + kvh) * 32 * 4096;
    const unsigned* Vf = g_vTh + (size_t)(b * NKV + kvh) * 32 * 4096;

    int nkt = qt + 1;

#define FA_ISSUE(kt_, bf_) do {                                               \
        unsigned base = smu_u + (bf_) * (FA_BUF * 4);                         \
        const unsigned* kp_ = Kf + (size_t)(kt_) * 4096;                      \
        const unsigned* vp_ = Vf + (size_t)(kt_) * 4096;                      \
        _Pragma("unroll")                                                     \
        for (int it = 0; it < 8; it++) {                                      \
            int c = tid + it * 128;                                           \
            cp_async16(base + c * 16, kp_ + c * 4);                           \
            cp_async16(base + 16384 + c * 16, vp_ + c * 4);                   \
        }                                                                     \
        CP_COMMIT();                                                          \
    } while (0)

    FA_ISSUE(0, 0);

    // Q fragments via LDG.128 (fragment-ordered by producer)
    unsigned qf[8][4];
    {
        int qblock = (b * SEQ + q0) / 16 + w;
        const unsigned* qb = g_qh + (((size_t)qblock * 16 + h) * 8) * 128 + lane * 4;
#pragma unroll
        for (int ks = 0; ks < 8; ks++) {
            uint4 q4 = *(const uint4*)(qb + ks * 128);
            qf[ks][0] = q4.x; qf[ks][1] = q4.y; qf[ks][2] = q4.z; qf[ks][3] = q4.w;
        }
    }

    float of[16][4];
#pragma unroll
    for (int j = 0; j < 16; j++)
#pragma unroll
        for (int c = 0; c < 4; c++) of[j][c] = 0.0f;
    float l0 = 0.0f, l1 = 0.0f;

    for (int kt = 0; kt < nkt; kt++) {
        int k0 = kt * 64;
        int buf = kt & 1;

        CP_WAIT(0);
        __syncthreads();

        if (kt + 1 < nkt) FA_ISSUE(kt + 1, buf ^ 1);

        unsigned* Ks = smu + buf * FA_BUF;
        unsigned* Vs = Ks + 4096;

        // --- S2 = Q @ K^T (base-2 domain), init with -8 bias ---
        float sf[8][4];
#pragma unroll
        for (int j = 0; j < 8; j++)
#pragma unroll
            for (int c = 0; c < 4; c++) sf[j][c] = -8.0f;

#pragma unroll
        for (int ks = 0; ks < 8; ks++) {
#pragma unroll
            for (int jp = 0; jp < 4; jp++) {
                uint4 k4 = *(uint4*)(Ks + ((ks * 4 + jp) * 32 + lane) * 4);
                mma_f16(sf[2 * jp],     qf[ks], k4.x, k4.y);
                mma_f16(sf[2 * jp + 1], qf[ks], k4.z, k4.w);
            }
        }

        if (kt == nkt - 1) {
#pragma unroll
            for (int j = 0; j < 8; j++) {
                int kg0 = k0 + j * 8 + 2 * t;
                if (kg0 > qrow0)     sf[j][0] = -1e30f;
                if (kg0 + 1 > qrow0) sf[j][1] = -1e30f;
                if (kg0 > qrow1)     sf[j][2] = -1e30f;
                if (kg0 + 1 > qrow1) sf[j][3] = -1e30f;
            }
        }

        // --- fixed-max softmax: P = 2^(S2 - 8) ---
#pragma unroll
        for (int j = 0; j < 8; j++) {
            sf[j][0] = ex2f(sf[j][0]);
            sf[j][1] = ex2f(sf[j][1]);
            sf[j][2] = ex2f(sf[j][2]);
            sf[j][3] = ex2f(sf[j][3]);
            l0 += sf[j][0] + sf[j][1];
            l1 += sf[j][2] + sf[j][3];
        }

        // --- P fragments directly from registers ---
        unsigned pf[4][4];
#pragma unroll
        for (int ks = 0; ks < 4; ks++) {
            pf[ks][0] = pack_h2(sf[2 * ks][0],     sf[2 * ks][1]);
            pf[ks][1] = pack_h2(sf[2 * ks][2],     sf[2 * ks][3]);
            pf[ks][2] = pack_h2(sf[2 * ks + 1][0], sf[2 * ks + 1][1]);
            pf[ks][3] = pack_h2(sf[2 * ks + 1][2], sf[2 * ks + 1][3]);
        }

        // --- O += P @ V (paired V) ---
#pragma unroll
        for (int ks = 0; ks < 4; ks++) {
#pragma unroll
            for (int jp = 0; jp < 8; jp++) {
                uint4 v4 = *(uint4*)(Vs + ((ks * 8 + jp) * 32 + lane) * 4);
                mma_f16(of[2 * jp],     pf[ks], v4.x, v4.y);
                mma_f16(of[2 * jp + 1], pf[ks], v4.z, v4.w);
            }
        }
    }
#undef FA_ISSUE

    l0 += __shfl_xor_sync(0xffffffffu, l0, 1);
    l0 += __shfl_xor_sync(0xffffffffu, l0, 2);
    l1 += __shfl_xor_sync(0xffffffffu, l1, 1);
    l1 += __shfl_xor_sync(0xffffffffu, l1, 2);

    // --- epilogue: write O in wo's A-fragment layout ---
    float inv0 = 1.0f / l0, inv1 = 1.0f / l1;
    int mtile_g = (b * SEQ + qrow0) >> 4;
    unsigned* ob = g_oh + (size_t)mtile_g * 128 * 128;
#pragma unroll
    for (int j = 0; j < 16; j++) {
        int ktile = h * 8 + (j >> 1);
        int idx = ktile * 128 + lane * 4 + (j & 1) * 2;
        uint2 u = make_uint2(pack_h2(of[j][0] * inv0, of[j][1] * inv0),
                             pack_h2(of[j][2] * inv1, of[j][3] * inv1));
        *(uint2*)(ob + idx) = u;
    }
}

// ---------------------------------------------------------------------------
// Launch
// ---------------------------------------------------------------------------
extern "C" void kernel_launch(void* const* d_in, const int* in_sizes, int n_in,
                              void* d_out, int out_size)
{
    const float* x  = (const float*)d_in[0];
    const float* Wq = (const float*)d_in[1];
    const float* Wk = (const float*)d_in[2];
    const float* Wv = (const float*)d_in[3];
    const float* Wo = (const float*)d_in[4];
    const float* qw = (const float*)d_in[5];
    const float* kw = (const float*)d_in[6];
    float* out = (float*)d_out;

    cudaFuncSetAttribute(qkv_h_kernel,
                         cudaFuncAttributeMaxDynamicSharedMemorySize, GEMM_SMEM);
    cudaFuncSetAttribute(wo_h_kernel,
                         cudaFuncAttributeMaxDynamicSharedMemorySize, GEMM_SMEM);
    cudaFuncSetAttribute(flash_h_kernel,
                         cudaFuncAttributeMaxDynamicSharedMemorySize, FA_SMEM);

    // zero output (split-K accumulates atomically into it)
    cudaMemsetAsync(out, 0, (size_t)out_size * sizeof(float));

    // fused coalesced prep (pack x + pack weights paired + rope)
    prep_kernel<<<8704, 256>>>(x, Wq, Wk, Wv, Wo);

    // fused QKV projection + RMSNorm + RoPE -> paired fragment layouts
    qkv_h_kernel<<<dim3(32, TOKENS / 128), 128, GEMM_SMEM>>>(qw, kw);

    // flash attention (R14 config)
    flash_h_kernel<<<dim3(SEQ / 64, NQ, BATCH), 128, FA_SMEM>>>();

    // output projection, split-K=2 with atomic combine
    wo_h_kernel<<<dim3(HIDDEN / 128, TOKENS / 128, 2), 128, GEMM_SMEM>>>(out);
}

// round 17
// speedup vs baseline: 1.0832x; 1.0832x over previous
#include <cuda_runtime.h>
#include <cuda_fp16.h>
#include <math.h>

// ---------------------------------------------------------------------------
// Problem constants
// ---------------------------------------------------------------------------
#define BATCH   2
#define SEQ     2048
#define HIDDEN  1024
#define Q_OUT   2048
#define KV_OUT  1024
#define HDIM    128
#define NQ      16
#define NKV     8
#define TOKENS  (BATCH*SEQ)          // 4096

// ---------------------------------------------------------------------------
// Scratch. All half2-packed uints, mma-fragment-ordered, PAIRED for LDS.128:
//   A-frag:  [mtile][ktile][lane(32)][reg(4)]
//   B-pair:  [kt][np=ng/2][lane(32)][reg(4)] reg=(ng&1)*2+r
//   K-pair:  [ktile][ksf(8)][jp(4)][lane][4]  reg=(jf&1)*2+r
//   V-pair:  [ktile][ksv(4)][jp(8)][lane][4]  reg=(jf&1)*2+r
//   Q-frag:  [qblock(tok/16)][h][ks(8)][lane][reg(4)]
// ---------------------------------------------------------------------------
__device__ __align__(256) unsigned g_xh [TOKENS/16 * 64 * 128];
__device__ __align__(256) unsigned g_wqh[64 * 128 * 128];            // npN=128
__device__ __align__(256) unsigned g_wkh[64 * 64 * 128];             // npN=64
__device__ __align__(256) unsigned g_wvh[64 * 64 * 128];
__device__ __align__(256) unsigned g_woh[128 * 64 * 128];
__device__ __align__(256) unsigned g_qh [TOKENS/16 * 16 * 8 * 128];  // Q frag
__device__ __align__(256) unsigned g_kTh[(size_t)BATCH * NKV * 32 * 4096];
__device__ __align__(256) unsigned g_vTh[(size_t)BATCH * NKV * 32 * 4096];
__device__ __align__(256) unsigned g_oh [TOKENS/16 * 128 * 128];     // wo A-frag
__device__ float g_cosT[SEQ * 64];
__device__ float g_sinT[SEQ * 64];

// ---------------------------------------------------------------------------
// helpers
// ---------------------------------------------------------------------------
__device__ __forceinline__ unsigned pack_h2(float lo, float hi) {
    unsigned u;
    asm("cvt.rn.f16x2.f32 %0, %2, %1;" : "=r"(u) : "f"(lo), "f"(hi));
    return u;
}

__device__ __forceinline__ float ex2f(float x) {
    float r;
    asm("ex2.approx.f32 %0, %1;" : "=f"(r) : "f"(x));
    return r;
}

__device__ __forceinline__ void mma_f16(float* c, const unsigned* a,
                                        unsigned b0, unsigned b1) {
    asm("mma.sync.aligned.m16n8k16.row.col.f32.f16.f16.f32 "
        "{%0,%1,%2,%3}, {%4,%5,%6,%7}, {%8,%9}, {%0,%1,%2,%3};"
        : "+f"(c[0]), "+f"(c[1]), "+f"(c[2]), "+f"(c[3])
        : "r"(a[0]), "r"(a[1]), "r"(a[2]), "r"(a[3]), "r"(b0), "r"(b1));
}

__device__ __forceinline__ void cp_async16(unsigned dst_smem, const void* src) {
    asm volatile("cp.async.cg.shared.global [%0], [%1], 16;\n"
                 :: "r"(dst_smem), "l"(src));
}
#define CP_COMMIT()  asm volatile("cp.async.commit_group;\n" ::: "memory")
#define CP_WAIT(N)   asm volatile("cp.async.wait_group %0;\n" :: "n"(N) : "memory")

// ---------------------------------------------------------------------------
// Fused prep (coalesced): x -> A-frag | weights -> B-pair | rope table
// ---------------------------------------------------------------------------
__global__ __launch_bounds__(256) void prep_kernel(
    const float* __restrict__ x,
    const float* __restrict__ Wq, const float* __restrict__ Wk,
    const float* __restrict__ Wv, const float* __restrict__ Wo)
{
    __shared__ float sm[16 * 132];
    int bid = blockIdx.x;
    int tid = threadIdx.x;

    if (bid < 2048) {
        int mtile = bid >> 3, ktg = bid & 7;
        const float* src = x + (size_t)mtile * 16 * 1024 + ktg * 128;
#pragma unroll
        for (int it = 0; it < 2; it++) {
            int p = tid + it * 256;
            int row = p >> 5, c4 = (p & 31) * 4;
            float4 v = *(const float4*)(src + (size_t)row * 1024 + c4);
            *(float4*)(sm + row * 132 + c4) = v;
        }
        __syncthreads();
#pragma unroll
        for (int it = 0; it < 4; it++) {
            int j = tid + it * 256;
            int ktl = j >> 7, i = j & 127;
            int gg = i >> 4, tt = (i >> 2) & 3, reg = i & 3;
            int ml = gg + (reg & 1) * 8;
            int cl = 2 * (ktl * 8 + tt + ((reg >> 1) & 1) * 4);
            g_xh[((size_t)mtile * 64 + ktg * 8 + ktl) * 128 + i] =
                pack_h2(sm[ml * 132 + cl], sm[ml * 132 + cl + 1]);
        }
        return;
    }
    if (bid < 8192) {
        int wb = bid - 2048;
        const float* src; unsigned* dst; int N, npN, kt, ngg;
        if (wb < 2048)      { src = Wq; dst = g_wqh; N = 2048; npN = 128; kt = wb >> 5; ngg = wb & 31; }
        else if (wb < 3072) { wb -= 2048; src = Wk; dst = g_wkh; N = 1024; npN = 64; kt = wb >> 4; ngg = wb & 15; }
        else if (wb < 4096) { wb -= 3072; src = Wv; dst = g_wvh; N = 1024; npN = 64; kt = wb >> 4; ngg = wb & 15; }
        else                { wb -= 4096; src = Wo; dst = g_woh; N = 1024; npN = 64; kt = wb >> 4; ngg = wb & 15; }
        {
            int row = tid >> 4, c4 = (tid & 15) * 4;
            float4 v = *(const float4*)(src + (size_t)(kt * 16 + row) * N + ngg * 64 + c4);
            *(float4*)(sm + row * 68 + c4) = v;
        }
        __syncthreads();
#pragma unroll
        for (int it = 0; it < 2; it++) {
            int j = tid + it * 256;                 // [0,512)
            int ngl = j >> 6, i = j & 63;
            int gg = i >> 3, tt = (i >> 1) & 3, reg = i & 1;
            int rl = 2 * (tt + reg * 4);
            int cl = ngl * 8 + gg;
            int ng = ngg * 8 + ngl;
            int lane = gg * 4 + tt;
            dst[((size_t)kt * npN + (ng >> 1)) * 128 + lane * 4 + (ng & 1) * 2 + reg] =
                pack_h2(sm[rl * 68 + cl], sm[(rl + 1) * 68 + cl]);
        }
        return;
    }
    int id = (bid - 8192) * 256 + tid;
    int t = id >> 6, j = id & 63;
    float e = (float)j * (1.0f / 64.0f);
    float inv = exp2f(-e * 13.287712379549449f);
    float a = (float)t * inv;
    float s, c;
    sincosf(a, &s, &c);
    g_cosT[t * 64 + j] = c;
    g_sinT[t * 64 + j] = s;
}

// ---------------------------------------------------------------------------
// fp16 GEMM core v8: BARRIER-FREE. Each warp owns a triple-buffered private
// staging region and cp.asyncs exactly the A/B rows it consumes. Pipeline
// sync is per-warp wait_group + __syncwarp only; warps free-run.
// Per warp per step: 16 cp.async + 16 LDS.128 -> 64 HMMA.
// ---------------------------------------------------------------------------
#define WBUF 2048                      // per warp per buffer: A 1024 + B 1024
#define GEMM_SMEM ((12 * WBUF + 512) * 4)   // 4 warps x 3 buffers + sred

__device__ __forceinline__ void gemm_core_wf(
    const unsigned* __restrict__ Ah, const unsigned* __restrict__ Bh,
    int NKT, int nkt, int npN, int mtile0, int np0,
    unsigned* dsm, float acc[4][8][4])
{
    int tid = threadIdx.x;
    int lane = tid & 31;
    int wi = tid >> 5;
    int warp_mi = (wi & 1) * 4;
    int wq = wi >> 1;

    unsigned* W = dsm + wi * 3 * WBUF;
    unsigned w_u = (unsigned)__cvta_generic_to_shared(W);

    const int nsteps = nkt >> 1;

    // A local rows: row = mi*2 + ks  (mi 0..3, ks 0..1), 128 uints each
    // B local rows: row = ks*4 + q   (npl = 2wq + (q&1) + (q>>1)*4)
#define GEMM_ISSUE(s, buf) do {                                               \
        unsigned base = w_u + (buf) * (WBUF * 4);                             \
        _Pragma("unroll")                                                     \
        for (int it = 0; it < 8; it++) {                                      \
            int c = lane + it * 32;                                           \
            int row = c >> 5, off = (c & 31) * 4;                             \
            cp_async16(base + (row * 128 + off) * 4,                          \
                Ah + ((size_t)(mtile0 + warp_mi + (row >> 1)) * NKT           \
                      + 2 * (s) + (row & 1)) * 128 + off);                    \
        }                                                                     \
        _Pragma("unroll")                                                     \
        for (int it = 0; it < 8; it++) {                                      \
            int c = lane + it * 32;                                           \
            int row = c >> 5, off = (c & 31) * 4;                             \
            int ksb = row >> 2, q = row & 3;                                  \
            int npl = 2 * wq + (q & 1) + (q >> 1) * 4;                        \
            cp_async16(base + 4096 + (row * 128 + off) * 4,                   \
                Bh + ((size_t)(2 * (s) + ksb) * npN + np0 + npl) * 128 + off);\
        }                                                                     \
        CP_COMMIT();                                                          \
    } while (0)

    GEMM_ISSUE(0, 0);
    GEMM_ISSUE(1, 1);

    int buf = 0;
    for (int s = 0; s < nsteps; s++) {
        CP_WAIT(1);
        __syncwarp();

        if (s + 2 < nsteps) {
            int nb = buf + 2; if (nb >= 3) nb -= 3;
            GEMM_ISSUE(s + 2, nb);
        } else {
            CP_COMMIT();
        }

        unsigned* Ab = W + buf * WBUF;
        unsigned* Bb = Ab + 1024;
#pragma unroll
        for (int ks = 0; ks < 2; ks++) {
            unsigned af[4][4];
            uint4 bf4[4];
#pragma unroll
            for (int mi = 0; mi < 4; mi++) {
                uint4 a4 = *(uint4*)(Ab + (mi * 2 + ks) * 128 + lane * 4);
                af[mi][0] = a4.x; af[mi][1] = a4.y; af[mi][2] = a4.z; af[mi][3] = a4.w;
            }
#pragma unroll
            for (int pq = 0; pq < 4; pq++) {
                bf4[pq] = *(uint4*)(Bb + (ks * 4 + pq) * 128 + lane * 4);
            }
#pragma unroll
            for (int mi = 0; mi < 4; mi++)
#pragma unroll
                for (int nj = 0; nj < 8; nj++) {
                    int pq = ((nj & 3) >> 1) + (nj >> 2) * 2;
                    unsigned b0 = (nj & 1) ? bf4[pq].z : bf4[pq].x;
                    unsigned b1 = (nj & 1) ? bf4[pq].w : bf4[pq].y;
                    mma_f16(acc[mi][nj], af[mi], b0, b1);
                }
        }

        buf++; if (buf == 3) buf = 0;
    }
#undef GEMM_ISSUE
}

// ---------------------------------------------------------------------------
// Fused QKV GEMM + RMSNorm + RoPE -> paired flash fragment layouts
// ---------------------------------------------------------------------------
__global__ __launch_bounds__(128, 2) void qkv_h_kernel(
    const float* __restrict__ qw, const float* __restrict__ kw)
{
    extern __shared__ unsigned dsm[];
    float (*sred)[2] = (float(*)[2])(dsm + 12 * WBUF);

    int bx = blockIdx.x;
    const unsigned* Bh; const float* w; int npN, np0, mode, head;
    if (bx < 16)      { Bh = g_wqh; npN = 128; np0 = bx * 8;        mode = 0; head = bx;      w = qw; }
    else if (bx < 24) { Bh = g_wkh; npN = 64;  np0 = (bx - 16) * 8; mode = 1; head = bx - 16; w = kw; }
    else              { Bh = g_wvh; npN = 64;  np0 = (bx - 24) * 8; mode = 2; head = bx - 24; w = qw; }

    int row0 = blockIdx.y * 128;

    float acc[4][8][4];
#pragma unroll
    for (int mi = 0; mi < 4; mi++)
#pragma unroll
        for (int nj = 0; nj < 8; nj++)
#pragma unroll
            for (int c = 0; c < 4; c++) acc[mi][nj][c] = 0.0f;

    gemm_core_wf(g_xh, Bh, 64, 64, npN, row0 >> 4, np0, dsm, acc);

    int tid = threadIdx.x;
    int lane = tid & 31;
    int wi = tid >> 5;
    int g = lane >> 2;
    int t = lane & 3;
    int warp_m = (wi & 1) * 64;
    int wq = wi >> 1;

    if (mode != 2) {
        float ssl[4][2];
#pragma unroll
        for (int mi = 0; mi < 4; mi++)
#pragma unroll
            for (int hf = 0; hf < 2; hf++) {
                float s = 0.0f;
#pragma unroll
                for (int nj = 0; nj < 8; nj++)
#pragma unroll
                    for (int b2 = 0; b2 < 2; b2++) {
                        float v = acc[mi][nj][hf * 2 + b2];
                        s = fmaf(v, v, s);
                    }
                s += __shfl_xor_sync(0xffffffffu, s, 1);
                s += __shfl_xor_sync(0xffffffffu, s, 2);
                ssl[mi][hf] = s;
            }
        __syncthreads();
        if (t == 0) {
#pragma unroll
            for (int mi = 0; mi < 4; mi++)
#pragma unroll
                for (int hf = 0; hf < 2; hf++)
                    sred[warp_m + mi * 16 + g + 8 * hf][wq] = ssl[mi][hf];
        }
        __syncthreads();

        float wv[8][2];
#pragma unroll
        for (int nj = 0; nj < 8; nj++) {
            int noff = (nj & 3) * 8 + (nj >> 2) * 64;
            wv[nj][0] = w[wq * 32 + noff + 2 * t];
            wv[nj][1] = w[wq * 32 + noff + 2 * t + 1];
        }

        const float qscale = 0.12751753972083234f;  // 1/sqrt(128)*log2e

#pragma unroll
        for (int mi = 0; mi < 4; mi++)
#pragma unroll
            for (int hf = 0; hf < 2; hf++) {
                int row = warp_m + mi * 16 + g + 8 * hf;
                float tot = sred[row][0] + sred[row][1];
                float r = rsqrtf(tot * (1.0f / 128.0f) + 1e-6f);
                int token = row0 + row;
                int tp = token & (SEQ - 1);
                int bb = token >> 11;

                float nv[8][2];
#pragma unroll
                for (int nj = 0; nj < 8; nj++)
#pragma unroll
                    for (int b2 = 0; b2 < 2; b2++)
                        nv[nj][b2] = acc[mi][nj][hf * 2 + b2] * r * wv[nj][b2];

#pragma unroll
                for (int nj = 0; nj < 8; nj++) {
                    int a = nj & 3, bq = nj >> 2;
                    int ci = wq * 32 + a * 8 + 2 * t;       // d & 63
                    float c0 = g_cosT[tp * 64 + ci];
                    float s0 = g_sinT[tp * 64 + ci];
                    float c1 = g_cosT[tp * 64 + ci + 1];
                    float s1 = g_sinT[tp * 64 + ci + 1];
                    float rot0 = (nj < 4) ? -nv[nj + 4][0] : nv[nj - 4][0];
                    float rot1 = (nj < 4) ? -nv[nj + 4][1] : nv[nj - 4][1];
                    float o0 = nv[nj][0] * c0 + rot0 * s0;
                    float o1 = nv[nj][1] * c1 + rot1 * s1;
                    if (mode == 0) {
                        int ks = wq * 2 + (a >> 1) + 4 * bq;
                        int qblock = token >> 4;
                        int reg = hf + (a & 1) * 2;
                        g_qh[((((size_t)qblock * 16 + head) * 8 + ks) * 32 + lane) * 4 + reg] =
                            pack_h2(o0 * qscale, o1 * qscale);
                    } else {
                        int dd = wq * 16 + a * 4 + bq * 32 + t;
                        int ksf = dd >> 3, rr = dd & 7;
                        int tf = rr & 3, regf = rr >> 2;
                        int ktile = tp >> 6;
                        int jf = (tp >> 3) & 7, gf = tp & 7;
                        size_t idx = ((size_t)(bb * NKV + head) * 32 + ktile) * 4096
                                   + ((ksf * 4 + (jf >> 1)) * 32 + gf * 4 + tf) * 4
                                   + (jf & 1) * 2 + regf;
                        g_kTh[idx] = pack_h2(o0, o1);
                    }
                }
            }
    } else {
#pragma unroll
        for (int mi = 0; mi < 4; mi++)
#pragma unroll
            for (int hf = 0; hf < 2; hf++) {
                int row = warp_m + mi * 16 + g + 8 * hf;
                int token = row0 + row;
                int tp = token & (SEQ - 1);
                int bb = token >> 11;
                int ktile = tp >> 6;
                int kkl = (tp & 63) >> 1;
                int ksv = kkl >> 3, rr = kkl & 7;
                int tf = rr & 3, regf = rr >> 2;
#pragma unroll
                for (int nj = 0; nj < 8; nj++) {
                    int noff = (nj & 3) * 8 + (nj >> 2) * 64;
                    float v0 = acc[mi][nj][hf * 2 + 0];
                    float v1 = acc[mi][nj][hf * 2 + 1];
                    float n0 = __shfl_down_sync(0xffffffffu, v0, 4);
                    float n1 = __shfl_down_sync(0xffffffffu, v1, 4);
                    if (!(g & 1)) {
                        int d0 = wq * 32 + noff + 2 * t;
                        int jf = d0 >> 3, gf = d0 & 7;
                        size_t idx = ((size_t)(bb * NKV + head) * 32 + ktile) * 4096
                                   + ((ksv * 8 + (jf >> 1)) * 32 + gf * 4 + tf) * 4
                                   + (jf & 1) * 2 + regf;
                        g_vTh[idx]      = pack_h2(v0, n0);
                        g_vTh[idx + 16] = pack_h2(v1, n1);
                    }
                }
            }
    }
}

// ---------------------------------------------------------------------------
// Wo GEMM (barrier-free core, full serial K)
// ---------------------------------------------------------------------------
__global__ __launch_bounds__(128, 2) void wo_h_kernel(float* __restrict__ C)
{
    extern __shared__ unsigned dsm[];

    int row0 = blockIdx.y * 128;
    int col0 = blockIdx.x * 128;

    float acc[4][8][4];
#pragma unroll
    for (int mi = 0; mi < 4; mi++)
#pragma unroll
        for (int nj = 0; nj < 8; nj++)
#pragma unroll
            for (int c = 0; c < 4; c++) acc[mi][nj][c] = 0.0f;

    gemm_core_wf(g_oh, g_woh, 128, 128, 64, row0 >> 4, col0 >> 4, dsm, acc);

    int tid = threadIdx.x;
    int lane = tid & 31;
    int wi = tid >> 5;
    int g = lane >> 2;
    int t = lane & 3;
    int warp_m = (wi & 1) * 64;
    int wq = wi >> 1;

#pragma unroll
    for (int mi = 0; mi < 4; mi++)
#pragma unroll
        for (int hf = 0; hf < 2; hf++) {
            int row = row0 + warp_m + mi * 16 + g + 8 * hf;
#pragma unroll
            for (int nj = 0; nj < 8; nj++) {
                int noff = (nj & 3) * 8 + (nj >> 2) * 64;
                float2 o2 = make_float2(acc[mi][nj][hf * 2 + 0],
                                        acc[mi][nj][hf * 2 + 1]);
                *(float2*)(C + (size_t)row * HIDDEN + col0 + wq * 32 + noff + 2 * t) = o2;
            }
        }
}

// ---------------------------------------------------------------------------
// Flash attention (R14, proven): paired K/V layouts, Q-frag LDG.128,
// fixed-max base-2 softmax, 64 q-rows / 128 threads, occupancy 3.
// ---------------------------------------------------------------------------
#define FA_BUF 8192
#define FA_SMEM (2 * FA_BUF * 4)

__global__ __launch_bounds__(128, 3) void flash_h_kernel()
{
    extern __shared__ unsigned smu[];
    unsigned smu_u = (unsigned)__cvta_generic_to_shared(smu);

    int qt = gridDim.x - 1 - blockIdx.x;   // big tiles first
    int h  = blockIdx.y;
    int b  = blockIdx.z;
    int kvh = h >> 1;
    int q0 = qt * 64;

    int tid = threadIdx.x;
    int w = tid >> 5;
    int lane = tid & 31;
    int g = lane >> 2;
    int t = lane & 3;

    int row0 = w * 16 + g;
    int row1 = row0 + 8;
    int qrow0 = q0 + row0;
    int qrow1 = q0 + row1;

    const unsigned* Kf = g_kTh + (size_t)(b * NKV + kvh) * 32 * 4096;
    const unsigned* Vf = g_vTh + (size_t)(b * NKV + kvh) * 32 * 4096;

    int nkt = qt + 1;

#define FA_ISSUE(kt_, bf_) do {                                               \
        unsigned base = smu_u + (bf_) * (FA_BUF * 4);                         \
        const unsigned* kp_ = Kf + (size_t)(kt_) * 4096;                      \
        const unsigned* vp_ = Vf + (size_t)(kt_) * 4096;                      \
        _Pragma("unroll")                                                     \
        for (int it = 0; it < 8; it++) {                                      \
            int c = tid + it * 128;                                           \
            cp_async16(base + c * 16, kp_ + c * 4);                           \
            cp_async16(base + 16384 + c * 16, vp_ + c * 4);                   \
        }                                                                     \
        CP_COMMIT();                                                          \
    } while (0)

    FA_ISSUE(0, 0);

    // Q fragments via LDG.128 (fragment-ordered by producer)
    unsigned qf[8][4];
    {
        int qblock = (b * SEQ + q0) / 16 + w;
        const unsigned* qb = g_qh + (((size_t)qblock * 16 + h) * 8) * 128 + lane * 4;
#pragma unroll
        for (int ks = 0; ks < 8; ks++) {
            uint4 q4 = *(const uint4*)(qb + ks * 128);
            qf[ks][0] = q4.x; qf[ks][1] = q4.y; qf[ks][2] = q4.z; qf[ks][3] = q4.w;
        }
    }

    float of[16][4];
#pragma unroll
    for (int j = 0; j < 16; j++)
#pragma unroll
        for (int c = 0; c < 4; c++) of[j][c] = 0.0f;
    float l0 = 0.0f, l1 = 0.0f;

    for (int kt = 0; kt < nkt; kt++) {
        int k0 = kt * 64;
        int buf = kt & 1;

        CP_WAIT(0);
        __syncthreads();

        if (kt + 1 < nkt) FA_ISSUE(kt + 1, buf ^ 1);

        unsigned* Ks = smu + buf * FA_BUF;
        unsigned* Vs = Ks + 4096;

        // --- S2 = Q @ K^T (base-2 domain), init with -8 bias ---
        float sf[8][4];
#pragma unroll
        for (int j = 0; j < 8; j++)
#pragma unroll
            for (int c = 0; c < 4; c++) sf[j][c] = -8.0f;

#pragma unroll
        for (int ks = 0; ks < 8; ks++) {
#pragma unroll
            for (int jp = 0; jp < 4; jp++) {
                uint4 k4 = *(uint4*)(Ks + ((ks * 4 + jp) * 32 + lane) * 4);
                mma_f16(sf[2 * jp],     qf[ks], k4.x, k4.y);
                mma_f16(sf[2 * jp + 1], qf[ks], k4.z, k4.w);
            }
        }

        if (kt == nkt - 1) {
#pragma unroll
            for (int j = 0; j < 8; j++) {
                int kg0 = k0 + j * 8 + 2 * t;
                if (kg0 > qrow0)     sf[j][0] = -1e30f;
                if (kg0 + 1 > qrow0) sf[j][1] = -1e30f;
                if (kg0 > qrow1)     sf[j][2] = -1e30f;
                if (kg0 + 1 > qrow1) sf[j][3] = -1e30f;
            }
        }

        // --- fixed-max softmax: P = 2^(S2 - 8) ---
#pragma unroll
        for (int j = 0; j < 8; j++) {
            sf[j][0] = ex2f(sf[j][0]);
            sf[j][1] = ex2f(sf[j][1]);
            sf[j][2] = ex2f(sf[j][2]);
            sf[j][3] = ex2f(sf[j][3]);
            l0 += sf[j][0] + sf[j][1];
            l1 += sf[j][2] + sf[j][3];
        }

        // --- P fragments directly from registers ---
        unsigned pf[4][4];
#pragma unroll
        for (int ks = 0; ks < 4; ks++) {
            pf[ks][0] = pack_h2(sf[2 * ks][0],     sf[2 * ks][1]);
            pf[ks][1] = pack_h2(sf[2 * ks][2],     sf[2 * ks][3]);
            pf[ks][2] = pack_h2(sf[2 * ks + 1][0], sf[2 * ks + 1][1]);
            pf[ks][3] = pack_h2(sf[2 * ks + 1][2], sf[2 * ks + 1][3]);
        }

        // --- O += P @ V (paired V) ---
#pragma unroll
        for (int ks = 0; ks < 4; ks++) {
#pragma unroll
            for (int jp = 0; jp < 8; jp++) {
                uint4 v4 = *(uint4*)(Vs + ((ks * 8 + jp) * 32 + lane) * 4);
                mma_f16(of[2 * jp],     pf[ks], v4.x, v4.y);
                mma_f16(of[2 * jp + 1], pf[ks], v4.z, v4.w);
            }
        }
    }
#undef FA_ISSUE

    l0 += __shfl_xor_sync(0xffffffffu, l0, 1);
    l0 += __shfl_xor_sync(0xffffffffu, l0, 2);
    l1 += __shfl_xor_sync(0xffffffffu, l1, 1);
    l1 += __shfl_xor_sync(0xffffffffu, l1, 2);

    // --- epilogue: write O in wo's A-fragment layout ---
    float inv0 = 1.0f / l0, inv1 = 1.0f / l1;
    int mtile_g = (b * SEQ + qrow0) >> 4;
    unsigned* ob = g_oh + (size_t)mtile_g * 128 * 128;
#pragma unroll
    for (int j = 0; j < 16; j++) {
        int ktile = h * 8 + (j >> 1);
        int idx = ktile * 128 + lane * 4 + (j & 1) * 2;
        uint2 u = make_uint2(pack_h2(of[j][0] * inv0, of[j][1] * inv0),
                             pack_h2(of[j][2] * inv1, of[j][3] * inv1));
        *(uint2*)(ob + idx) = u;
    }
}

// ---------------------------------------------------------------------------
// Launch
// ---------------------------------------------------------------------------
extern "C" void kernel_launch(void* const* d_in, const int* in_sizes, int n_in,
                              void* d_out, int out_size)
{
    const float* x  = (const float*)d_in[0];
    const float* Wq = (const float*)d_in[1];
    const float* Wk = (const float*)d_in[2];
    const float* Wv = (const float*)d_in[3];
    const float* Wo = (const float*)d_in[4];
    const float* qw = (const float*)d_in[5];
    const float* kw = (const float*)d_in[6];
    float* out = (float*)d_out;

    cudaFuncSetAttribute(qkv_h_kernel,
                         cudaFuncAttributeMaxDynamicSharedMemorySize, GEMM_SMEM);
    cudaFuncSetAttribute(wo_h_kernel,
                         cudaFuncAttributeMaxDynamicSharedMemorySize, GEMM_SMEM);
    cudaFuncSetAttribute(flash_h_kernel,
                         cudaFuncAttributeMaxDynamicSharedMemorySize, FA_SMEM);

    // fused coalesced prep (pack x + pack weights paired + rope)
    prep_kernel<<<8704, 256>>>(x, Wq, Wk, Wv, Wo);

    // fused QKV projection + RMSNorm + RoPE -> paired fragment layouts
    qkv_h_kernel<<<dim3(32, TOKENS / 128), 128, GEMM_SMEM>>>(qw, kw);

    // flash attention (R14 config)
    flash_h_kernel<<<dim3(SEQ / 64, NQ, BATCH), 128, FA_SMEM>>>();

    // output projection (barrier-free core)
    wo_h_kernel<<<dim3(HIDDEN / 128, TOKENS / 128), 128, GEMM_SMEM>>>(out);
}